// round 7
// baseline (speedup 1.0000x reference)
#include <cuda_runtime.h>
#include <stdint.h>

#define NUM_CLASSES 32000
#define C4 (NUM_CLASSES / 4)        // 8000 float4 slots per row
#define ALPHA 0.95f
#define THREADS 512
#define NWARP (THREADS / 32)
#define RITEMS 9                    // float4s/thread in registers (9*512 = 4608 slots)
#define RSLOTS (RITEMS * THREADS)   // 4608
#define SSLOTS (C4 - RSLOTS)        // 3392 slots staged in smem
#define SITER 7                     // ceil(3392/512); last iter: tid < 320
#define SMEM_DYN_BYTES (2 * SSLOTS * 16)   // double buffer: 108544 B

__device__ __forceinline__ int load_label(const void* labels, int row, int is64) {
    if (is64) return (int)(((const long long*)labels)[row]);
    return ((const int*)labels)[row];
}

// Persistent, 2 CTAs/SM, software-pipelined across rows.
// Row staged once: 9 float4/thread in regs + 3392 float4 in double-buffered
// smem (thread-private slots -> no buffer-swap barrier). Next row's loads are
// issued between the current row's two store bursts, so the CTA's DRAM stream
// stays mixed read/write except during the single per-row reduce barrier
// (covered by the co-resident CTA).
__global__ __launch_bounds__(THREADS, 2)
void distill_kernel(const float* __restrict__ x,
                    const void*  __restrict__ labels,
                    float*       __restrict__ out,
                    int nrows) {
    extern __shared__ float4 s4[];                 // 2 * SSLOTS
    __shared__ float warp_sums[2][NWARP];          // double-buffered partials

    const int tid  = threadIdx.x;
    const int lane = tid & 31;
    const int wid  = tid >> 5;
    const int stride = gridDim.x;

    // Inline label-dtype detection: probe 4 u64 words (in-bounds for both
    // int64[batch] and int32[batch] layouts since batch/2 >= 4). int64 labels
    // are all < 32000; an int32 buffer read as u64 is < 32000 only when the
    // odd-position label is 0 — P(4 in a row) ~ (1/32000)^4 ~ 1e-18.
    const unsigned long long* lu = (const unsigned long long*)labels;
    const int is64 = !((lu[0] >= (unsigned long long)NUM_CLASSES) |
                       (lu[1] >= (unsigned long long)NUM_CLASSES) |
                       (lu[2] >= (unsigned long long)NUM_CLASSES) |
                       (lu[3] >= (unsigned long long)NUM_CLASSES));

    int row = blockIdx.x;
    if (row >= nrows) return;

    float4 v[RITEMS];
    float  S_cur, t_cur;
    int    lab_cur;
    int    b = 0;                                  // current smem buffer

    // ---- Prologue: stage first row, reduce its sum ----
    {
        lab_cur = load_label(labels, row, is64);
        t_cur = __ldg(x + (size_t)row * NUM_CLASSES + lab_cur);
        const float4* __restrict__ xr = reinterpret_cast<const float4*>(x + (size_t)row * NUM_CLASSES);
        float sum = 0.0f;
        #pragma unroll
        for (int k = 0; k < RITEMS; k++) {
            v[k] = __ldcs(&xr[tid + k * THREADS]);
            sum += (v[k].x + v[k].y) + (v[k].z + v[k].w);
        }
        #pragma unroll
        for (int k = 0; k < SITER; k++) {
            const int j = tid + k * THREADS;
            if (k < SITER - 1 || j < SSLOTS) {
                float4 w = __ldcs(&xr[RSLOTS + j]);
                s4[j] = w;                          // buffer 0
                sum += (w.x + w.y) + (w.z + w.w);
            }
        }
        #pragma unroll
        for (int off = 16; off > 0; off >>= 1)
            sum += __shfl_down_sync(0xffffffffu, sum, off);
        if (lane == 0) warp_sums[0][wid] = sum;
        __syncthreads();
        float S = 0.0f;
        #pragma unroll
        for (int w = 0; w < NWARP; w++) S += warp_sums[0][w];
        S_cur = S;
    }

    // ---- Main pipelined loop ----
    while (row < nrows) {
        const int rn = row + stride;               // next row (uniform per CTA)

        const float s    = ALPHA / (1.0f + S_cur - 2.0f * t_cur);
        const float corr = 1.0f - s * S_cur;
        const int lab4 = lab_cur >> 2;
        const int labc = lab_cur & 3;

        float4* __restrict__ buf_cur = s4 + b * SSLOTS;
        float4* __restrict__ buf_nxt = s4 + (b ^ 1) * SSLOTS;
        float4* __restrict__ orow = reinterpret_cast<float4*>(out + (size_t)row * NUM_CLASSES);

        float sum_n = 0.0f;
        int   lab_n = 0;
        float t_n   = 0.0f;

        // (A) next row: smem-portion loads into the other buffer
        if (rn < nrows) {
            lab_n = load_label(labels, rn, is64);
            t_n = __ldg(x + (size_t)rn * NUM_CLASSES + lab_n);
            const float4* __restrict__ xrn = reinterpret_cast<const float4*>(x + (size_t)rn * NUM_CLASSES);
            #pragma unroll
            for (int k = 0; k < SITER; k++) {
                const int j = tid + k * THREADS;
                if (k < SITER - 1 || j < SSLOTS) {
                    float4 w = __ldcs(&xrn[RSLOTS + j]);
                    buf_nxt[j] = w;
                    sum_n += (w.x + w.y) + (w.z + w.w);
                }
            }
        }

        // (B) store current reg portion (frees v)
        #pragma unroll
        for (int k = 0; k < RITEMS; k++) {
            const int i = tid + k * THREADS;
            float4 o;
            o.x = s * v[k].x;
            o.y = s * v[k].y;
            o.z = s * v[k].z;
            o.w = s * v[k].w;
            if (i == lab4) reinterpret_cast<float*>(&o)[labc] += corr;
            __stcs(&orow[i], o);
        }

        // (C) next row: reg-portion loads
        if (rn < nrows) {
            const float4* __restrict__ xrn = reinterpret_cast<const float4*>(x + (size_t)rn * NUM_CLASSES);
            #pragma unroll
            for (int k = 0; k < RITEMS; k++) {
                v[k] = __ldcs(&xrn[tid + k * THREADS]);
                sum_n += (v[k].x + v[k].y) + (v[k].z + v[k].w);
            }
        }

        // (D) store current smem portion
        #pragma unroll
        for (int k = 0; k < SITER; k++) {
            const int j = tid + k * THREADS;
            if (k < SITER - 1 || j < SSLOTS) {
                float4 w = buf_cur[j];
                const int i = RSLOTS + j;
                float4 o;
                o.x = s * w.x;
                o.y = s * w.y;
                o.z = s * w.z;
                o.w = s * w.w;
                if (i == lab4) reinterpret_cast<float*>(&o)[labc] += corr;
                __stcs(&orow[i], o);
            }
        }

        // Reduce next row's sum — single barrier per row (uniform branch).
        if (rn < nrows) {
            float a = sum_n;
            #pragma unroll
            for (int off = 16; off > 0; off >>= 1)
                a += __shfl_down_sync(0xffffffffu, a, off);
            const int rb = b ^ 1;
            if (lane == 0) warp_sums[rb][wid] = a;
            __syncthreads();
            float S = 0.0f;
            #pragma unroll
            for (int w = 0; w < NWARP; w++) S += warp_sums[rb][w];
            S_cur = S;
            t_cur = t_n;
            lab_cur = lab_n;
        }

        row = rn;
        b ^= 1;
    }
}

extern "C" void kernel_launch(void* const* d_in, const int* in_sizes, int n_in,
                              void* d_out, int out_size) {
    const float* teacher_logits = (const float*)d_in[0];
    const void*  true_labels    = d_in[1];
    float* out = (float*)d_out;

    const int batch = in_sizes[1];   // 4096 rows

    int dev = 0, nsm = 148;
    cudaGetDevice(&dev);
    cudaDeviceGetAttribute(&nsm, cudaDevAttrMultiProcessorCount, dev);

    cudaFuncSetAttribute(distill_kernel,
                         cudaFuncAttributeMaxDynamicSharedMemorySize, SMEM_DYN_BYTES);

    distill_kernel<<<2 * nsm, THREADS, SMEM_DYN_BYTES>>>(teacher_logits, true_labels, out, batch);
}

// round 8
// speedup vs baseline: 1.1459x; 1.1459x over previous
#include <cuda_runtime.h>
#include <stdint.h>

#define NUM_CLASSES 32000
#define C4 (NUM_CLASSES / 4)        // 8000 float4 slots per row
#define ALPHA 0.95f
#define THREADS 512
#define NWARP (THREADS / 32)        // 16
#define RITEMS 10                   // float4s per thread in registers
#define RSLOTS (RITEMS * THREADS)   // 5120 slots in regs
#define SSLOTS (C4 - RSLOTS)        // 2880 slots in smem
#define SITER  ((SSLOTS + THREADS - 1) / THREADS)   // 6 (last iter: tid < 320)
#define SMEM_STAGE_BYTES (SSLOTS * 16)              // 46080 B

// R4 structure (best known): one CTA per row, 2 CTAs/SM as independent
// barrier domains; row staged once (10 float4/thread in regs + 2880 float4 in
// smem, thread-private slots -> no staging barrier). Exactly 1 DRAM read +
// 1 DRAM write per element. R8 deltas vs R4: plain stores (no __stcs),
// single-barrier reduce, inline label-dtype detection.
__global__ __launch_bounds__(THREADS, 2)
void distill_kernel(const float* __restrict__ x,
                    const void*  __restrict__ labels,
                    float*       __restrict__ out) {
    __shared__ float4 s4[SSLOTS];           // thread-private staging slots
    __shared__ float  warp_sums[NWARP];

    const int row = blockIdx.x;
    const int tid = threadIdx.x;

    const float4* __restrict__ xr   = reinterpret_cast<const float4*>(x + (size_t)row * NUM_CLASSES);
    float4*       __restrict__ orow = reinterpret_cast<float4*>(out + (size_t)row * NUM_CLASSES);

    // Inline label-dtype detection: probe 4 u64 words (in-bounds for both
    // int64[4096] and int32[4096] layouts). True int64 labels are all
    // < 32000; an int32 buffer viewed as u64 is < 32000 only when the
    // odd-position label is exactly 0 — P(4 in a row) ~ (1/32000)^4 ~ 1e-18.
    const unsigned long long* lu = (const unsigned long long*)labels;
    const bool is64 = (lu[0] < (unsigned long long)NUM_CLASSES) &
                      (lu[1] < (unsigned long long)NUM_CLASSES) &
                      (lu[2] < (unsigned long long)NUM_CLASSES) &
                      (lu[3] < (unsigned long long)NUM_CLASSES);

    // Label + t issued early so their latency hides under the bulk loads.
    int lab;
    if (is64) lab = (int)(((const long long*)labels)[row]);
    else      lab = ((const int*)labels)[row];
    const float t = __ldg(x + (size_t)row * NUM_CLASSES + lab);

    // ---- Phase 1a: 10 float4/thread into registers (deep MLP) ----
    float4 v[RITEMS];
    float sum = 0.0f;
    #pragma unroll
    for (int k = 0; k < RITEMS; k++) {
        v[k] = __ldcs(&xr[tid + k * THREADS]);
        sum += (v[k].x + v[k].y) + (v[k].z + v[k].w);
    }
    // ---- Phase 1b: remaining 2880 float4 staged in smem (thread-private) ----
    #pragma unroll
    for (int k = 0; k < SITER; k++) {
        const int j = tid + k * THREADS;
        if (k < SITER - 1 || j < SSLOTS) {
            float4 w = __ldcs(&xr[RSLOTS + j]);
            s4[j] = w;
            sum += (w.x + w.y) + (w.z + w.w);
        }
    }

    // ---- Single-barrier block reduce ----
    #pragma unroll
    for (int off = 16; off > 0; off >>= 1)
        sum += __shfl_down_sync(0xffffffffu, sum, off);
    const int lane = tid & 31;
    const int wid  = tid >> 5;
    if (lane == 0) warp_sums[wid] = sum;
    __syncthreads();
    // Every thread folds the 16 partials (broadcast LDS, conflict-free).
    float S = 0.0f;
    #pragma unroll
    for (int w = 0; w < NWARP; w++) S += warp_sums[w];

    const float s = ALPHA / (1.0f + S - 2.0f * t);
    const float corr = 1.0f - s * S;

    const int lab4 = lab >> 2;
    const int labc = lab & 3;

    // ---- Phase 2a: scale registers + fused label correction, plain stores ----
    #pragma unroll
    for (int k = 0; k < RITEMS; k++) {
        const int i = tid + k * THREADS;
        float4 o;
        o.x = s * v[k].x;
        o.y = s * v[k].y;
        o.z = s * v[k].z;
        o.w = s * v[k].w;
        if (i == lab4) reinterpret_cast<float*>(&o)[labc] += corr;
        orow[i] = o;
    }
    // ---- Phase 2b: scale smem-staged part ----
    #pragma unroll
    for (int k = 0; k < SITER; k++) {
        const int j = tid + k * THREADS;
        if (k < SITER - 1 || j < SSLOTS) {
            float4 w = s4[j];
            const int i = RSLOTS + j;
            float4 o;
            o.x = s * w.x;
            o.y = s * w.y;
            o.z = s * w.z;
            o.w = s * w.w;
            if (i == lab4) reinterpret_cast<float*>(&o)[labc] += corr;
            orow[i] = o;
        }
    }
}

extern "C" void kernel_launch(void* const* d_in, const int* in_sizes, int n_in,
                              void* d_out, int out_size) {
    const float* teacher_logits = (const float*)d_in[0];
    const void*  true_labels    = d_in[1];
    float* out = (float*)d_out;

    const int batch = in_sizes[1];   // 4096 rows

    distill_kernel<<<batch, THREADS>>>(teacher_logits, true_labels, out);
}

// round 9
// speedup vs baseline: 1.1463x; 1.0004x over previous
#include <cuda_runtime.h>
#include <stdint.h>

#define NUM_CLASSES 32000
#define C4 (NUM_CLASSES / 4)        // 8000 float4 slots per row
#define ALPHA 0.95f
#define THREADS 512
#define NWARP (THREADS / 32)        // 16
#define RITEMS 4                    // float4s per thread in registers (small -> low regs)
#define RSLOTS (RITEMS * THREADS)   // 2048 slots staged in regs
#define TSLOTS (C4 - RSLOTS)        // 5952 tail slots, L2-resident re-read
#define TITER  ((TSLOTS + THREADS - 1) / THREADS)   // 12 (last iter: tid < 320)

// Cache-tiered hybrid: one CTA per row, 3 CTAs/SM (48 warps, 3 independent
// barrier domains, zero smem staging).
//   - 2048 slots/row staged in registers (__ldcs: single-use, evict-first)
//   - 5952 tail slots read with __ldg (evict-normal -> retained in L2) and
//     RE-READ from L2 in phase 2. Tail is read last in phase 1 and re-read
//     first in phase 2, minimizing the eviction window; tail working set
//     (~93 KB x ~444 resident CTAs ~ 41 MB) fits the 126 MB L2.
__global__ __launch_bounds__(THREADS, 3)
void distill_kernel(const float* __restrict__ x,
                    const void*  __restrict__ labels,
                    float*       __restrict__ out) {
    __shared__ float warp_sums[NWARP];

    const int row = blockIdx.x;
    const int tid = threadIdx.x;

    const float4* __restrict__ xr   = reinterpret_cast<const float4*>(x + (size_t)row * NUM_CLASSES);
    float4*       __restrict__ orow = reinterpret_cast<float4*>(out + (size_t)row * NUM_CLASSES);

    // Inline label-dtype detection: probe 4 u64 words (in-bounds for both
    // int64[4096] and int32[4096] layouts). True int64 labels are all
    // < 32000; an int32 buffer viewed as u64 is < 32000 only when the
    // odd-position label is exactly 0 — P(4 in a row) ~ (1/32000)^4 ~ 1e-18.
    const unsigned long long* lu = (const unsigned long long*)labels;
    const bool is64 = (lu[0] < (unsigned long long)NUM_CLASSES) &
                      (lu[1] < (unsigned long long)NUM_CLASSES) &
                      (lu[2] < (unsigned long long)NUM_CLASSES) &
                      (lu[3] < (unsigned long long)NUM_CLASSES);

    // Label + t issued early so their latency hides under the bulk loads.
    int lab;
    if (is64) lab = (int)(((const long long*)labels)[row]);
    else      lab = ((const int*)labels)[row];
    const float t = __ldg(x + (size_t)row * NUM_CLASSES + lab);

    // ---- Phase 1a: 4 float4/thread into registers (single-use, evict-first) ----
    float4 v[RITEMS];
    float sum = 0.0f;
    #pragma unroll
    for (int k = 0; k < RITEMS; k++) {
        v[k] = __ldcs(&xr[tid + k * THREADS]);
        sum += (v[k].x + v[k].y) + (v[k].z + v[k].w);
    }
    // ---- Phase 1b: tail read with L2 retention (will be re-read in phase 2) ----
    #pragma unroll
    for (int k = 0; k < TITER; k++) {
        const int j = tid + k * THREADS;
        if (k < TITER - 1 || j < TSLOTS) {
            const float4 w = __ldg(&xr[RSLOTS + j]);
            sum += (w.x + w.y) + (w.z + w.w);
        }
    }

    // ---- Single-barrier block reduce ----
    #pragma unroll
    for (int off = 16; off > 0; off >>= 1)
        sum += __shfl_down_sync(0xffffffffu, sum, off);
    if ((tid & 31) == 0) warp_sums[tid >> 5] = sum;
    __syncthreads();
    float S = 0.0f;
    #pragma unroll
    for (int w = 0; w < NWARP; w++) S += warp_sums[w];

    const float s = ALPHA / (1.0f + S - 2.0f * t);
    const float corr = 1.0f - s * S;

    const int lab4 = lab >> 2;
    const int labc = lab & 3;

    // ---- Phase 2a: tail FIRST (hottest in L2), re-read + scale + store ----
    #pragma unroll
    for (int k = 0; k < TITER; k++) {
        const int j = tid + k * THREADS;
        if (k < TITER - 1 || j < TSLOTS) {
            const int i = RSLOTS + j;
            const float4 w = __ldg(&xr[i]);
            float4 o;
            o.x = s * w.x;
            o.y = s * w.y;
            o.z = s * w.z;
            o.w = s * w.w;
            if (i == lab4) reinterpret_cast<float*>(&o)[labc] += corr;
            orow[i] = o;
        }
    }
    // ---- Phase 2b: register part, scale + fused label correction ----
    #pragma unroll
    for (int k = 0; k < RITEMS; k++) {
        const int i = tid + k * THREADS;
        float4 o;
        o.x = s * v[k].x;
        o.y = s * v[k].y;
        o.z = s * v[k].z;
        o.w = s * v[k].w;
        if (i == lab4) reinterpret_cast<float*>(&o)[labc] += corr;
        orow[i] = o;
    }
}

extern "C" void kernel_launch(void* const* d_in, const int* in_sizes, int n_in,
                              void* d_out, int out_size) {
    const float* teacher_logits = (const float*)d_in[0];
    const void*  true_labels    = d_in[1];
    float* out = (float*)d_out;

    const int batch = in_sizes[1];   // 4096 rows

    distill_kernel<<<batch, THREADS>>>(teacher_logits, true_labels, out);
}

// round 11
// speedup vs baseline: 1.1665x; 1.0176x over previous
#include <cuda_runtime.h>
#include <stdint.h>

#define NUM_CLASSES 32000
#define C4 (NUM_CLASSES / 4)        // 8000 float4 slots per row
#define ALPHA 0.95f
#define THREADS 512
#define NWARP (THREADS / 32)        // 16
#define RITEMS 4                    // float4s per thread in registers
#define RSLOTS (RITEMS * THREADS)   // 2048 slots staged in regs
#define TSLOTS (C4 - RSLOTS)        // 5952 tail float4 slots
#define T8     (TSLOTS / 2)         // 2976 32-byte chunks (TSLOTS even)
#define T8ITER ((T8 + THREADS - 1) / THREADS)       // 6 (last iter: tid < 416)

// 256-bit tail load with L2::evict_last (sm_103a requires .v4.b64/.v8.b32 for
// this modifier). One instruction covers 2 float4s; returns the 8-float sum
// contribution and nothing else (values are re-read from L2 in phase 2).
__device__ __forceinline__ float ldg_el_sum32(const void* p) {
    unsigned long long x0, x1, x2, x3;
    asm volatile("ld.global.L2::evict_last.v4.b64 {%0,%1,%2,%3}, [%4];"
                 : "=l"(x0), "=l"(x1), "=l"(x2), "=l"(x3) : "l"(p));
    float a, b, c, d, e, f, g, h;
    asm("mov.b64 {%0,%1}, %2;" : "=f"(a), "=f"(b) : "l"(x0));
    asm("mov.b64 {%0,%1}, %2;" : "=f"(c), "=f"(d) : "l"(x1));
    asm("mov.b64 {%0,%1}, %2;" : "=f"(e), "=f"(f) : "l"(x2));
    asm("mov.b64 {%0,%1}, %2;" : "=f"(g), "=f"(h) : "l"(x3));
    return ((a + b) + (c + d)) + ((e + f) + (g + h));
}

// Cache-tiered hybrid (R9 structure + explicit L2 policy, 256-bit tail loads):
//   - one CTA per row, 3 CTAs/SM (48 warps, 3 independent barrier domains,
//     zero smem staging -> no STS/LDS contention with LDG issue)
//   - 2048 slots/row in registers (__ldcs, single-use)
//   - 5952 tail slots: phase-1 read as 32-B LDG.256 with L2::evict_last
//     (pinned in L2), phase-2 re-read tail-FIRST with __ldcs (dead after),
//   - stores __stcs (evict-first write-allocate: don't churn the tail set)
__global__ __launch_bounds__(THREADS, 3)
void distill_kernel(const float* __restrict__ x,
                    const void*  __restrict__ labels,
                    float*       __restrict__ out) {
    __shared__ float warp_sums[NWARP];

    const int row = blockIdx.x;
    const int tid = threadIdx.x;

    const float4* __restrict__ xr   = reinterpret_cast<const float4*>(x + (size_t)row * NUM_CLASSES);
    float4*       __restrict__ orow = reinterpret_cast<float4*>(out + (size_t)row * NUM_CLASSES);

    // Inline label-dtype detection: probe 4 u64 words (in-bounds for both
    // int64[4096] and int32[4096] layouts). True int64 labels are all
    // < 32000; an int32 buffer viewed as u64 is < 32000 only when the
    // odd-position label is exactly 0 — P(4 in a row) ~ (1/32000)^4 ~ 1e-18.
    const unsigned long long* lu = (const unsigned long long*)labels;
    const bool is64 = (lu[0] < (unsigned long long)NUM_CLASSES) &
                      (lu[1] < (unsigned long long)NUM_CLASSES) &
                      (lu[2] < (unsigned long long)NUM_CLASSES) &
                      (lu[3] < (unsigned long long)NUM_CLASSES);

    // Label + t issued early so their latency hides under the bulk loads.
    int lab;
    if (is64) lab = (int)(((const long long*)labels)[row]);
    else      lab = ((const int*)labels)[row];
    const float t = __ldg(x + (size_t)row * NUM_CLASSES + lab);

    // ---- Phase 1a: 4 float4/thread into registers (single-use, evict-first) ----
    float4 v[RITEMS];
    float sum = 0.0f;
    #pragma unroll
    for (int k = 0; k < RITEMS; k++) {
        v[k] = __ldcs(&xr[tid + k * THREADS]);
        sum += (v[k].x + v[k].y) + (v[k].z + v[k].w);
    }
    // ---- Phase 1b: tail as 32-B LDG.256, pinned evict_last in L2 ----
    const char* tail_base = reinterpret_cast<const char*>(xr + RSLOTS);
    #pragma unroll
    for (int k = 0; k < T8ITER; k++) {
        const int j = tid + k * THREADS;
        if (k < T8ITER - 1 || j < T8) {
            sum += ldg_el_sum32(tail_base + (size_t)j * 32);
        }
    }

    // ---- Single-barrier block reduce ----
    #pragma unroll
    for (int off = 16; off > 0; off >>= 1)
        sum += __shfl_down_sync(0xffffffffu, sum, off);
    if ((tid & 31) == 0) warp_sums[tid >> 5] = sum;
    __syncthreads();
    float S = 0.0f;
    #pragma unroll
    for (int w = 0; w < NWARP; w++) S += warp_sums[w];

    const float s = ALPHA / (1.0f + S - 2.0f * t);
    const float corr = 1.0f - s * S;

    const int lab4 = lab >> 2;
    const int labc = lab & 3;

    // ---- Phase 2a: tail FIRST (hot, evict_last in L2); re-read evict-first ----
    #pragma unroll
    for (int k = 0; k < 2 * T8ITER; k++) {          // 12 float4 iterations
        const int j = tid + k * THREADS;
        if (k < 2 * T8ITER - 1 || j < TSLOTS) {
            const int i = RSLOTS + j;
            const float4 w = __ldcs(&xr[i]);
            float4 o;
            o.x = s * w.x;
            o.y = s * w.y;
            o.z = s * w.z;
            o.w = s * w.w;
            if (i == lab4) reinterpret_cast<float*>(&o)[labc] += corr;
            __stcs(&orow[i], o);
        }
    }
    // ---- Phase 2b: register part, scale + fused label correction ----
    #pragma unroll
    for (int k = 0; k < RITEMS; k++) {
        const int i = tid + k * THREADS;
        float4 o;
        o.x = s * v[k].x;
        o.y = s * v[k].y;
        o.z = s * v[k].z;
        o.w = s * v[k].w;
        if (i == lab4) reinterpret_cast<float*>(&o)[labc] += corr;
        __stcs(&orow[i], o);
    }
}

extern "C" void kernel_launch(void* const* d_in, const int* in_sizes, int n_in,
                              void* d_out, int out_size) {
    const float* teacher_logits = (const float*)d_in[0];
    const void*  true_labels    = d_in[1];
    float* out = (float*)d_out;

    const int batch = in_sizes[1];   // 4096 rows

    distill_kernel<<<batch, THREADS>>>(teacher_logits, true_labels, out);
}

// round 12
// speedup vs baseline: 1.1753x; 1.0075x over previous
#include <cuda_runtime.h>
#include <stdint.h>

#define NUM_CLASSES 32000
#define C4 (NUM_CLASSES / 4)        // 8000 float4 slots per row
#define ALPHA 0.95f
#define THREADS 512
#define NWARP (THREADS / 32)        // 16
#define RITEMS 4                    // float4s per thread in registers
#define RSLOTS (RITEMS * THREADS)   // 2048 slots staged in regs
#define TSLOTS (C4 - RSLOTS)        // 5952 tail float4 slots
#define T8     (TSLOTS / 2)         // 2976 32-byte chunks (TSLOTS even)
#define T8ITER ((T8 + THREADS - 1) / THREADS)       // 6 (last iter: tid < 416)

// 256-bit tail load with L2::evict_last. NOT volatile: these are pure loads at
// distinct addresses, and letting the compiler hoist/batch them preserves MLP.
// Outputs land directly in b32 regs (free bit-cast to float, no mov.b64 unpack).
__device__ __forceinline__ float ldg_el_sum32(const void* p) {
    unsigned u0, u1, u2, u3, u4, u5, u6, u7;
    asm("ld.global.L2::evict_last.v8.b32 {%0,%1,%2,%3,%4,%5,%6,%7}, [%8];"
        : "=r"(u0), "=r"(u1), "=r"(u2), "=r"(u3),
          "=r"(u4), "=r"(u5), "=r"(u6), "=r"(u7)
        : "l"(p));
    const float a = __uint_as_float(u0), b = __uint_as_float(u1);
    const float c = __uint_as_float(u2), d = __uint_as_float(u3);
    const float e = __uint_as_float(u4), f = __uint_as_float(u5);
    const float g = __uint_as_float(u6), h = __uint_as_float(u7);
    return ((a + b) + (c + d)) + ((e + f) + (g + h));
}

// Cache-tiered hybrid:
//   - one CTA per row, 3 CTAs/SM (48 warps, 3 independent barrier domains,
//     zero smem staging -> no STS/LDS contention with LDG issue)
//   - 2048 slots/row in registers (__ldcs, single-use)
//   - 5952 tail slots: phase-1 read as 32-B LDG.256 with L2::evict_last
//     (pinned in L2 -> floor DRAM traffic, proven in R11), phase-2 re-read
//     tail-FIRST with __ldcs (dead after the read)
//   - plain stores (best-rate store config from R9)
__global__ __launch_bounds__(THREADS, 3)
void distill_kernel(const float* __restrict__ x,
                    const void*  __restrict__ labels,
                    float*       __restrict__ out) {
    __shared__ float warp_sums[NWARP];

    const int row = blockIdx.x;
    const int tid = threadIdx.x;

    const float4* __restrict__ xr   = reinterpret_cast<const float4*>(x + (size_t)row * NUM_CLASSES);
    float4*       __restrict__ orow = reinterpret_cast<float4*>(out + (size_t)row * NUM_CLASSES);

    // Inline label-dtype detection: probe 4 u64 words (in-bounds for both
    // int64[4096] and int32[4096] layouts). True int64 labels are all
    // < 32000; an int32 buffer viewed as u64 is < 32000 only when the
    // odd-position label is exactly 0 — P(4 in a row) ~ (1/32000)^4 ~ 1e-18.
    const unsigned long long* lu = (const unsigned long long*)labels;
    const bool is64 = (lu[0] < (unsigned long long)NUM_CLASSES) &
                      (lu[1] < (unsigned long long)NUM_CLASSES) &
                      (lu[2] < (unsigned long long)NUM_CLASSES) &
                      (lu[3] < (unsigned long long)NUM_CLASSES);

    // Label + t issued early so their latency hides under the bulk loads.
    int lab;
    if (is64) lab = (int)(((const long long*)labels)[row]);
    else      lab = ((const int*)labels)[row];
    const float t = __ldg(x + (size_t)row * NUM_CLASSES + lab);

    // ---- Phase 1a: 4 float4/thread into registers (single-use, evict-first) ----
    float4 v[RITEMS];
    float sum = 0.0f;
    #pragma unroll
    for (int k = 0; k < RITEMS; k++) {
        v[k] = __ldcs(&xr[tid + k * THREADS]);
        sum += (v[k].x + v[k].y) + (v[k].z + v[k].w);
    }
    // ---- Phase 1b: tail as 32-B LDG.256, pinned evict_last in L2 ----
    const char* tail_base = reinterpret_cast<const char*>(xr + RSLOTS);
    #pragma unroll
    for (int k = 0; k < T8ITER; k++) {
        const int j = tid + k * THREADS;
        if (k < T8ITER - 1 || j < T8) {
            sum += ldg_el_sum32(tail_base + (size_t)j * 32);
        }
    }

    // ---- Single-barrier block reduce ----
    #pragma unroll
    for (int off = 16; off > 0; off >>= 1)
        sum += __shfl_down_sync(0xffffffffu, sum, off);
    if ((tid & 31) == 0) warp_sums[tid >> 5] = sum;
    __syncthreads();
    float S = 0.0f;
    #pragma unroll
    for (int w = 0; w < NWARP; w++) S += warp_sums[w];

    const float s = ALPHA / (1.0f + S - 2.0f * t);
    const float corr = 1.0f - s * S;

    const int lab4 = lab >> 2;
    const int labc = lab & 3;

    // ---- Phase 2a: tail FIRST (hot, evict_last in L2); re-read evict-first ----
    #pragma unroll
    for (int k = 0; k < 2 * T8ITER; k++) {          // 12 float4 iterations
        const int j = tid + k * THREADS;
        if (k < 2 * T8ITER - 1 || j < TSLOTS) {
            const int i = RSLOTS + j;
            const float4 w = __ldcs(&xr[i]);
            float4 o;
            o.x = s * w.x;
            o.y = s * w.y;
            o.z = s * w.z;
            o.w = s * w.w;
            if (i == lab4) reinterpret_cast<float*>(&o)[labc] += corr;
            orow[i] = o;
        }
    }
    // ---- Phase 2b: register part, scale + fused label correction ----
    #pragma unroll
    for (int k = 0; k < RITEMS; k++) {
        const int i = tid + k * THREADS;
        float4 o;
        o.x = s * v[k].x;
        o.y = s * v[k].y;
        o.z = s * v[k].z;
        o.w = s * v[k].w;
        if (i == lab4) reinterpret_cast<float*>(&o)[labc] += corr;
        orow[i] = o;
    }
}

extern "C" void kernel_launch(void* const* d_in, const int* in_sizes, int n_in,
                              void* d_out, int out_size) {
    const float* teacher_logits = (const float*)d_in[0];
    const void*  true_labels    = d_in[1];
    float* out = (float*)d_out;

    const int batch = in_sizes[1];   // 4096 rows

    distill_kernel<<<batch, THREADS>>>(teacher_logits, true_labels, out);
}